// round 4
// baseline (speedup 1.0000x reference)
#include <cuda_runtime.h>
#include <math.h>

#define Nn 10000
#define Ee 160000
#define Ff 4
#define Hh 32
#define Cc 4

// ---------------- scratch (device globals; no allocation allowed) -----------
__device__ float g_Qn[Nn * Hh * Hh];       // per-node Q matrices [N, H, H] (40MB)
__device__ float g_r [Nn * Hh];            // per-node b2 contribution r[n,o]
__device__ float g_xA[Nn * Hh];            // ping-pong node features (pre-relu)
__device__ float g_xB[Nn * Hh];
__device__ float g_msg[Ee * Hh];           // per-edge messages (20MB)
__device__ int    g_cntS[Nn], g_curS[Nn];  // src counting sort
__device__ int    g_cntD[Nn], g_curD[Nn];  // dst counting sort
__device__ int    g_offS[Nn + 1];          // CSR by src
__device__ int    g_offD[Nn + 1];          // CSR by dst
__device__ int    g_didx[Ee];              // dst-CSR -> index into src-sorted arrays
__device__ float2 g_sea [Ee];              // edge_attr sorted by src

// ---------------------------------------------------------------------------
__global__ void zero_kernel() {
    int t = blockIdx.x * blockDim.x + threadIdx.x;
    if (t < Nn) { g_cntS[t] = 0; g_curS[t] = 0; g_cntD[t] = 0; g_curD[t] = 0; }
}

__global__ void hist_kernel(const int* __restrict__ ei) {
    int base = (blockIdx.x * blockDim.x + threadIdx.x) * 4;
#pragma unroll
    for (int j = 0; j < 4; j++) {
        int t = base + j;
        if (t < Ee) {
            atomicAdd(&g_cntS[ei[t]], 1);
            atomicAdd(&g_cntD[ei[Ee + t]], 1);
        }
    }
}

__global__ void scan_kernel(const int* __restrict__ cnt, int* __restrict__ off) {
    __shared__ int partial[1024];
    const int tid = threadIdx.x;
    const int base = tid * 10;                 // 1024*10 >= 10000
    int s = 0;
    for (int j = 0; j < 10; j++) {
        int idx = base + j;
        if (idx < Nn) s += cnt[idx];
    }
    partial[tid] = s;
    __syncthreads();
    for (int d = 1; d < 1024; d <<= 1) {
        int v = 0;
        if (tid >= d) v = partial[tid - d];
        __syncthreads();
        if (tid >= d) partial[tid] += v;
        __syncthreads();
    }
    int run = (tid > 0) ? partial[tid - 1] : 0;
    for (int j = 0; j < 10; j++) {
        int idx = base + j;
        if (idx < Nn) { off[idx] = run; run += cnt[idx]; }
    }
    if (tid == 1023) off[Nn] = run;
}

__global__ void scatter_kernel(const int* __restrict__ ei,
                               const float* __restrict__ ea) {
    int base = (blockIdx.x * blockDim.x + threadIdx.x) * 4;
#pragma unroll
    for (int j = 0; j < 4; j++) {
        int t = base + j;
        if (t < Ee) {
            int s = ei[t];
            int d = ei[Ee + t];
            int p = g_offS[s] + atomicAdd(&g_curS[s], 1);
            int q = g_offD[d] + atomicAdd(&g_curD[d], 1);
            g_sea[p]  = reinterpret_cast<const float2*>(ea)[t];
            g_didx[q] = p;
        }
    }
}

// ---------------------------------------------------------------------------
// fused Qn + aux (f32x2 FMA GEMM): see round-2 comments.
// ---------------------------------------------------------------------------
template <int DIN, bool RELU>
__global__ void qnaux_kernel(const float* __restrict__ x,
                             const float* __restrict__ w2,
                             const float* __restrict__ root,
                             const float* __restrict__ bias,
                             const float* __restrict__ b2,
                             float* __restrict__ Qn,
                             float* __restrict__ agg,
                             float* __restrict__ rbuf) {
    __shared__ float2 xs2[8][DIN];
    const int nbase = blockIdx.x * 8;
    const int tid = threadIdx.x;

    for (int idx = tid; idx < 8 * DIN; idx += 128) {
        int t = idx / DIN, i = idx % DIN;
        float v = x[(nbase + t) * DIN + i];
        if (RELU) v = fmaxf(v, 0.f);
        xs2[t][i] = make_float2(v, v);
    }
    __syncthreads();

    const int c0 = tid * 8;
    const int k  = c0 >> 5;
    const int ob = c0 & 31;
    const float* wbase = w2 + k * (DIN * Hh) + ob;

    unsigned long long acc[8][4];
#pragma unroll
    for (int t = 0; t < 8; t++)
#pragma unroll
        for (int p = 0; p < 4; p++) acc[t][p] = 0ULL;

#pragma unroll
    for (int i = 0; i < DIN; i++) {
        ulonglong2 wa = *reinterpret_cast<const ulonglong2*>(wbase + i * Hh);
        ulonglong2 wb = *reinterpret_cast<const ulonglong2*>(wbase + i * Hh + 4);
#pragma unroll
        for (int t = 0; t < 8; t++) {
            unsigned long long xv =
                *reinterpret_cast<const unsigned long long*>(&xs2[t][i]);
            asm("fma.rn.f32x2 %0,%1,%2,%0;" : "+l"(acc[t][0]) : "l"(xv), "l"(wa.x));
            asm("fma.rn.f32x2 %0,%1,%2,%0;" : "+l"(acc[t][1]) : "l"(xv), "l"(wa.y));
            asm("fma.rn.f32x2 %0,%1,%2,%0;" : "+l"(acc[t][2]) : "l"(xv), "l"(wb.x));
            asm("fma.rn.f32x2 %0,%1,%2,%0;" : "+l"(acc[t][3]) : "l"(xv), "l"(wb.y));
        }
    }

#pragma unroll
    for (int t = 0; t < 8; t++) {
        float* dst = Qn + (nbase + t) * (Hh * Hh) + c0;
#pragma unroll
        for (int p = 0; p < 4; p++)
            *reinterpret_cast<unsigned long long*>(dst + p * 2) = acc[t][p];
    }

    for (int it = tid; it < 256; it += 128) {
        int t = it >> 5, o = it & 31;
        float accA = 0.f, accR = 0.f;
#pragma unroll
        for (int i = 0; i < DIN; i++) {
            float xv = xs2[t][i].x;
            accA = fmaf(xv, root[i * Hh + o], accA);
            accR = fmaf(xv, b2  [i * Hh + o], accR);
        }
        agg [(nbase + t) * Hh + o] = accA + bias[o];
        rbuf[(nbase + t) * Hh + o] = accR;
    }
}

// ---------------------------------------------------------------------------
// edge stage, src-sorted, NO atomics: one warp per src node, 32-edge tiles.
// Writes per-edge messages to g_msg at the src-sorted position (coalesced).
// ---------------------------------------------------------------------------
__global__ void edge4_kernel(const float* __restrict__ w1,
                             const float* __restrict__ b1,
                             const float* __restrict__ Qn,
                             const float* __restrict__ rbuf) {
    __shared__ float hs_all[8][32][32];
    const int wip  = threadIdx.x >> 5;
    const int n    = (blockIdx.x * blockDim.x + threadIdx.x) >> 5;
    const int lane = threadIdx.x & 31;
    if (n >= Nn) return;
    const int beg = g_offS[n], end = g_offS[n + 1];
    if (beg == end) return;
    float (*hs)[32] = hs_all[wip];

    const float w1a = w1[lane], w1b = w1[Hh + lane], b1v = b1[lane];

    float qreg[Hh];
    const float* __restrict__ q = Qn + n * (Hh * Hh) + lane;
#pragma unroll
    for (int k = 0; k < Hh; k++) qreg[k] = q[k * Hh];
    const float rsrc = rbuf[n * Hh + lane];

    for (int t = beg; t < end; t += 32) {
        const int m = min(32, end - t);
        float2 eav = make_float2(0.f, 0.f);
        if (lane < m) eav = g_sea[t + lane];

        // phase 1: h for each edge in tile (lane = k)
        for (int e = 0; e < m; e++) {
            float ea0 = __shfl_sync(0xffffffffu, eav.x, e);
            float ea1 = __shfl_sync(0xffffffffu, eav.y, e);
            hs[e][lane] = fmaxf(fmaf(ea0, w1a, fmaf(ea1, w1b, b1v)), 0.f);
        }
        __syncwarp();

        // phase 2: msg = r + Q^T h, streamed store (no atomics)
        for (int e = 0; e < m; e++) {
            const float4* hv = reinterpret_cast<const float4*>(hs[e]);
            float a0 = rsrc, a1 = 0.f, a2 = 0.f, a3 = 0.f;
#pragma unroll
            for (int c = 0; c < 8; c++) {
                float4 h4 = hv[c];
                a0 = fmaf(h4.x, qreg[4 * c    ], a0);
                a1 = fmaf(h4.y, qreg[4 * c + 1], a1);
                a2 = fmaf(h4.z, qreg[4 * c + 2], a2);
                a3 = fmaf(h4.w, qreg[4 * c + 3], a3);
            }
            g_msg[(t + e) * Hh + lane] = (a0 + a1) + (a2 + a3);
        }
        __syncwarp();
    }
}

// ---------------------------------------------------------------------------
// reduce stage, dst-CSR: one warp per dst node, gather msg rows, add to init.
// ---------------------------------------------------------------------------
__global__ void reduce_kernel(float* __restrict__ agg) {
    const int n    = (blockIdx.x * blockDim.x + threadIdx.x) >> 5;
    const int lane = threadIdx.x & 31;
    if (n >= Nn) return;
    const int beg = g_offD[n], end = g_offD[n + 1];
    if (beg == end) return;

    float acc = 0.f;
    int e = beg;
    for (; e + 1 < end; e += 2) {
        int p0 = g_didx[e], p1 = g_didx[e + 1];
        acc += g_msg[p0 * Hh + lane] + g_msg[p1 * Hh + lane];
    }
    if (e < end) acc += g_msg[g_didx[e] * Hh + lane];
    agg[n * Hh + lane] += acc;
}

// ---------------------------------------------------------------------------
__global__ void fc_kernel(const float* __restrict__ xr,
                          const float* __restrict__ fcw,
                          const float* __restrict__ fcb,
                          float* __restrict__ out) {
    int warp = (blockIdx.x * blockDim.x + threadIdx.x) >> 5;
    int lane = threadIdx.x & 31;
    if (warp >= Nn) return;

    float xv = fmaxf(xr[warp * Hh + lane], 0.f);
    float lg[Cc];
#pragma unroll
    for (int c = 0; c < Cc; c++) {
        float p = xv * fcw[lane * Cc + c];
#pragma unroll
        for (int s = 16; s > 0; s >>= 1)
            p += __shfl_xor_sync(0xffffffffu, p, s);
        lg[c] = p + fcb[c];
    }
    float m = fmaxf(fmaxf(lg[0], lg[1]), fmaxf(lg[2], lg[3]));
    float se = 0.f;
#pragma unroll
    for (int c = 0; c < Cc; c++) se += __expf(lg[c] - m);
    float lse = m + __logf(se);
    if (lane < Cc) out[warp * Cc + lane] = lg[lane] - lse;
}

// ---------------------------------------------------------------------------
extern "C" void kernel_launch(void* const* d_in, const int* in_sizes, int n_in,
                              void* d_out, int out_size) {
    (void)in_sizes; (void)n_in; (void)out_size;

    const float* x  = (const float*)d_in[0];
    const int*   ei = (const int*)  d_in[1];
    const float* ea = (const float*)d_in[2];
    const float* w1[3];  const float* b1[3];  const float* w2[3];
    const float* b2[3];  const float* rt[3];  const float* bs[3];
    for (int l = 0; l < 3; l++) {
        w1[l] = (const float*)d_in[3 + 6 * l + 0];
        b1[l] = (const float*)d_in[3 + 6 * l + 1];
        w2[l] = (const float*)d_in[3 + 6 * l + 2];
        b2[l] = (const float*)d_in[3 + 6 * l + 3];
        rt[l] = (const float*)d_in[3 + 6 * l + 4];
        bs[l] = (const float*)d_in[3 + 6 * l + 5];
    }
    const float* fcw = (const float*)d_in[21];
    const float* fcb = (const float*)d_in[22];
    float* out = (float*)d_out;

    float *Qn, *rbuf, *xA, *xB;
    int *cntS, *cntD, *offS, *offD;
    cudaGetSymbolAddress((void**)&Qn,   g_Qn);
    cudaGetSymbolAddress((void**)&rbuf, g_r);
    cudaGetSymbolAddress((void**)&xA,   g_xA);
    cudaGetSymbolAddress((void**)&xB,   g_xB);
    cudaGetSymbolAddress((void**)&cntS, g_cntS);
    cudaGetSymbolAddress((void**)&cntD, g_cntD);
    cudaGetSymbolAddress((void**)&offS, g_offS);
    cudaGetSymbolAddress((void**)&offD, g_offD);

    const int qnBlocks       = Nn / 8;                 // 1250
    const int nodeWarpBlocks = (Nn * 32 + 255) / 256;  // 1250
    const int e4Blocks       = (Ee / 4 + 255) / 256;   // 157

    // ---------------- dual counting sort (by src and by dst) ------------
    zero_kernel<<<(Nn + 1023) / 1024, 1024>>>();
    hist_kernel<<<e4Blocks, 256>>>(ei);
    scan_kernel<<<1, 1024>>>(cntS, offS);
    scan_kernel<<<1, 1024>>>(cntD, offD);
    scatter_kernel<<<e4Blocks, 256>>>(ei, ea);

    // ---------------- layer 0 (din=4, input not relu'd) ----------------
    qnaux_kernel<Ff, false><<<qnBlocks, 128>>>(x,  w2[0], rt[0], bs[0], b2[0], Qn, xA, rbuf);
    edge4_kernel<<<nodeWarpBlocks, 256>>>(w1[0], b1[0], Qn, rbuf);
    reduce_kernel<<<nodeWarpBlocks, 256>>>(xA);

    // ---------------- layer 1 -------------------------------------------
    qnaux_kernel<Hh, true ><<<qnBlocks, 128>>>(xA, w2[1], rt[1], bs[1], b2[1], Qn, xB, rbuf);
    edge4_kernel<<<nodeWarpBlocks, 256>>>(w1[1], b1[1], Qn, rbuf);
    reduce_kernel<<<nodeWarpBlocks, 256>>>(xB);

    // ---------------- layer 2 -------------------------------------------
    qnaux_kernel<Hh, true ><<<qnBlocks, 128>>>(xB, w2[2], rt[2], bs[2], b2[2], Qn, xA, rbuf);
    edge4_kernel<<<nodeWarpBlocks, 256>>>(w1[2], b1[2], Qn, rbuf);
    reduce_kernel<<<nodeWarpBlocks, 256>>>(xA);

    // ---------------- FC + log_softmax ----------------------------------
    fc_kernel<<<nodeWarpBlocks, 256>>>(xA, fcw, fcb, out);
}

// round 7
// speedup vs baseline: 1.0595x; 1.0595x over previous
#include <cuda_runtime.h>
#include <math.h>

#define Nn 10000
#define Ee 160000
#define Ff 4
#define Hh 32
#define Cc 4

// ---------------- scratch (device globals; no allocation allowed) -----------
__device__ float g_Qn[Nn * Hh * Hh];       // per-node Q matrices [N, H, H] (40MB)
__device__ float g_r [Nn * Hh];            // per-node b2 contribution r[n,o]
__device__ float g_xA[Nn * Hh];            // ping-pong node features (pre-relu)
__device__ float g_xB[Nn * Hh];
__device__ int    g_cnt[Nn];               // counting sort: histogram
__device__ int    g_cur[Nn];               // counting sort: scatter cursors
__device__ int    g_off[Nn + 1];           // CSR offsets by src
__device__ int    g_sdst[Ee];              // dst sorted by src
__device__ float2 g_sea [Ee];              // edge_attr sorted by src

// ---------------------------------------------------------------------------
__global__ void zero_kernel() {
    int t = blockIdx.x * blockDim.x + threadIdx.x;
    if (t < Nn) { g_cnt[t] = 0; g_cur[t] = 0; }
}

__global__ void hist_kernel(const int* __restrict__ ei) {
    int base = (blockIdx.x * blockDim.x + threadIdx.x) * 4;
#pragma unroll
    for (int j = 0; j < 4; j++) {
        int t = base + j;
        if (t < Ee) atomicAdd(&g_cnt[ei[t]], 1);
    }
}

// warp-shfl scan: 1024 threads x 10 items, 2 barriers total
__global__ void scan_kernel() {
    __shared__ int wsum[32];
    const int tid  = threadIdx.x;
    const int lane = tid & 31, wid = tid >> 5;
    const int base = tid * 10;

    int loc[10];
    int s = 0;
#pragma unroll
    for (int j = 0; j < 10; j++) {
        int idx = base + j;
        int v = (idx < Nn) ? g_cnt[idx] : 0;
        loc[j] = s;                 // exclusive within thread
        s += v;
    }
    int t = s;                      // inclusive warp scan of per-thread sums
#pragma unroll
    for (int d = 1; d < 32; d <<= 1) {
        int u = __shfl_up_sync(0xffffffffu, t, d);
        if (lane >= d) t += u;
    }
    if (lane == 31) wsum[wid] = t;
    __syncthreads();
    if (wid == 0) {
        int w = wsum[lane];
#pragma unroll
        for (int d = 1; d < 32; d <<= 1) {
            int u = __shfl_up_sync(0xffffffffu, w, d);
            if (lane >= d) w += u;
        }
        wsum[lane] = w;
    }
    __syncthreads();
    int prefix = t - s + (wid > 0 ? wsum[wid - 1] : 0);
#pragma unroll
    for (int j = 0; j < 10; j++) {
        int idx = base + j;
        if (idx < Nn) g_off[idx] = prefix + loc[j];
    }
    if (tid == 1023) g_off[Nn] = wsum[31];
}

__global__ void scatter_kernel(const int* __restrict__ ei,
                               const float* __restrict__ ea) {
    int base = (blockIdx.x * blockDim.x + threadIdx.x) * 4;
#pragma unroll
    for (int j = 0; j < 4; j++) {
        int t = base + j;
        if (t < Ee) {
            int s = ei[t];
            int p = g_off[s] + atomicAdd(&g_cur[s], 1);
            g_sdst[p] = ei[Ee + t];
            g_sea[p]  = reinterpret_cast<const float2*>(ea)[t];
        }
    }
}

// ---------------------------------------------------------------------------
// fused Qn + aux (f32x2 FMA GEMM)
// ---------------------------------------------------------------------------
template <int DIN, bool RELU>
__global__ void qnaux_kernel(const float* __restrict__ x,
                             const float* __restrict__ w2,
                             const float* __restrict__ root,
                             const float* __restrict__ bias,
                             const float* __restrict__ b2,
                             float* __restrict__ Qn,
                             float* __restrict__ agg,
                             float* __restrict__ rbuf) {
    __shared__ float2 xs2[8][DIN];
    const int nbase = blockIdx.x * 8;
    const int tid = threadIdx.x;

    for (int idx = tid; idx < 8 * DIN; idx += 128) {
        int t = idx / DIN, i = idx % DIN;
        float v = x[(nbase + t) * DIN + i];
        if (RELU) v = fmaxf(v, 0.f);
        xs2[t][i] = make_float2(v, v);
    }
    __syncthreads();

    const int c0 = tid * 8;
    const int k  = c0 >> 5;
    const int ob = c0 & 31;
    const float* wbase = w2 + k * (DIN * Hh) + ob;

    unsigned long long acc[8][4];
#pragma unroll
    for (int t = 0; t < 8; t++)
#pragma unroll
        for (int p = 0; p < 4; p++) acc[t][p] = 0ULL;

#pragma unroll
    for (int i = 0; i < DIN; i++) {
        ulonglong2 wa = *reinterpret_cast<const ulonglong2*>(wbase + i * Hh);
        ulonglong2 wb = *reinterpret_cast<const ulonglong2*>(wbase + i * Hh + 4);
#pragma unroll
        for (int t = 0; t < 8; t++) {
            unsigned long long xv =
                *reinterpret_cast<const unsigned long long*>(&xs2[t][i]);
            asm("fma.rn.f32x2 %0,%1,%2,%0;" : "+l"(acc[t][0]) : "l"(xv), "l"(wa.x));
            asm("fma.rn.f32x2 %0,%1,%2,%0;" : "+l"(acc[t][1]) : "l"(xv), "l"(wa.y));
            asm("fma.rn.f32x2 %0,%1,%2,%0;" : "+l"(acc[t][2]) : "l"(xv), "l"(wb.x));
            asm("fma.rn.f32x2 %0,%1,%2,%0;" : "+l"(acc[t][3]) : "l"(xv), "l"(wb.y));
        }
    }

#pragma unroll
    for (int t = 0; t < 8; t++) {
        float* dst = Qn + (nbase + t) * (Hh * Hh) + c0;
#pragma unroll
        for (int p = 0; p < 4; p++)
            *reinterpret_cast<unsigned long long*>(dst + p * 2) = acc[t][p];
    }

    for (int it = tid; it < 256; it += 128) {
        int t = it >> 5, o = it & 31;
        float accA = 0.f, accR = 0.f;
#pragma unroll
        for (int i = 0; i < DIN; i++) {
            float xv = xs2[t][i].x;
            accA = fmaf(xv, root[i * Hh + o], accA);
            accR = fmaf(xv, b2  [i * Hh + o], accR);
        }
        agg [(nbase + t) * Hh + o] = accA + bias[o];
        rbuf[(nbase + t) * Hh + o] = accR;
    }
}

// ---------------------------------------------------------------------------
// edge stage, src-sorted: one warp per node, 32-edge tiles.
// Phase 1: h tile via shfl broadcast + STS.
// Phase 2: 8x LDS.128 broadcast + 32 FMA, then gather 4 lanes -> 1 and emit
//          red.global.add.v4.f32 (4x fewer atomic ops than scalar atomicAdd).
// ---------------------------------------------------------------------------
__global__ void edge5_kernel(const float* __restrict__ w1,
                             const float* __restrict__ b1,
                             const float* __restrict__ Qn,
                             const float* __restrict__ rbuf,
                             float* __restrict__ agg) {
    __shared__ float hs_all[8][32][32];        // 32KB: per-warp h tile
    const int wip  = threadIdx.x >> 5;
    const int n    = (blockIdx.x * blockDim.x + threadIdx.x) >> 5;
    const int lane = threadIdx.x & 31;
    if (n >= Nn) return;
    const int beg = g_off[n], end = g_off[n + 1];
    if (beg == end) return;
    float (*hs)[32] = hs_all[wip];

    const float w1a = w1[lane], w1b = w1[Hh + lane], b1v = b1[lane];

    float qreg[Hh];
    const float* __restrict__ q = Qn + n * (Hh * Hh) + lane;
#pragma unroll
    for (int k = 0; k < Hh; k++) qreg[k] = q[k * Hh];
    const float rsrc = rbuf[n * Hh + lane];

    for (int t = beg; t < end; t += 32) {
        const int m = min(32, end - t);
        float2 eav = make_float2(0.f, 0.f);
        int dstv = 0;
        if (lane < m) { eav = g_sea[t + lane]; dstv = g_sdst[t + lane]; }

        // phase 1: h for each edge in tile (lane = k)
        for (int e = 0; e < m; e++) {
            float ea0 = __shfl_sync(0xffffffffu, eav.x, e);
            float ea1 = __shfl_sync(0xffffffffu, eav.y, e);
            hs[e][lane] = fmaxf(fmaf(ea0, w1a, fmaf(ea1, w1b, b1v)), 0.f);
        }
        __syncwarp();

        // phase 2: msg = r + Q^T h; vectorized reduction to agg[dst]
        for (int e = 0; e < m; e++) {
            int dst = __shfl_sync(0xffffffffu, dstv, e);
            const float4* hv = reinterpret_cast<const float4*>(hs[e]);
            float a0 = rsrc, a1 = 0.f, a2 = 0.f, a3 = 0.f;
#pragma unroll
            for (int c = 0; c < 8; c++) {
                float4 h4 = hv[c];
                a0 = fmaf(h4.x, qreg[4 * c    ], a0);
                a1 = fmaf(h4.y, qreg[4 * c + 1], a1);
                a2 = fmaf(h4.z, qreg[4 * c + 2], a2);
                a3 = fmaf(h4.w, qreg[4 * c + 3], a3);
            }
            float v0 = (a0 + a1) + (a2 + a3);                 // msg[lane]
            float v1 = __shfl_down_sync(0xffffffffu, v0, 1);
            float v2 = __shfl_down_sync(0xffffffffu, v0, 2);
            float v3 = __shfl_down_sync(0xffffffffu, v0, 3);
            if ((lane & 3) == 0) {
                asm volatile("red.global.add.v4.f32 [%0], {%1,%2,%3,%4};"
                             :: "l"(&agg[dst * Hh + lane]),
                                "f"(v0), "f"(v1), "f"(v2), "f"(v3)
                             : "memory");
            }
        }
        __syncwarp();
    }
}

// ---------------------------------------------------------------------------
__global__ void fc_kernel(const float* __restrict__ xr,
                          const float* __restrict__ fcw,
                          const float* __restrict__ fcb,
                          float* __restrict__ out) {
    int warp = (blockIdx.x * blockDim.x + threadIdx.x) >> 5;
    int lane = threadIdx.x & 31;
    if (warp >= Nn) return;

    float xv = fmaxf(xr[warp * Hh + lane], 0.f);
    float lg[Cc];
#pragma unroll
    for (int c = 0; c < Cc; c++) {
        float p = xv * fcw[lane * Cc + c];
#pragma unroll
        for (int s = 16; s > 0; s >>= 1)
            p += __shfl_xor_sync(0xffffffffu, p, s);
        lg[c] = p + fcb[c];
    }
    float m = fmaxf(fmaxf(lg[0], lg[1]), fmaxf(lg[2], lg[3]));
    float se = 0.f;
#pragma unroll
    for (int c = 0; c < Cc; c++) se += __expf(lg[c] - m);
    float lse = m + __logf(se);
    if (lane < Cc) out[warp * Cc + lane] = lg[lane] - lse;
}

// ---------------------------------------------------------------------------
extern "C" void kernel_launch(void* const* d_in, const int* in_sizes, int n_in,
                              void* d_out, int out_size) {
    (void)in_sizes; (void)n_in; (void)out_size;

    const float* x  = (const float*)d_in[0];
    const int*   ei = (const int*)  d_in[1];
    const float* ea = (const float*)d_in[2];
    const float* w1[3];  const float* b1[3];  const float* w2[3];
    const float* b2[3];  const float* rt[3];  const float* bs[3];
    for (int l = 0; l < 3; l++) {
        w1[l] = (const float*)d_in[3 + 6 * l + 0];
        b1[l] = (const float*)d_in[3 + 6 * l + 1];
        w2[l] = (const float*)d_in[3 + 6 * l + 2];
        b2[l] = (const float*)d_in[3 + 6 * l + 3];
        rt[l] = (const float*)d_in[3 + 6 * l + 4];
        bs[l] = (const float*)d_in[3 + 6 * l + 5];
    }
    const float* fcw = (const float*)d_in[21];
    const float* fcb = (const float*)d_in[22];
    float* out = (float*)d_out;

    float *Qn, *rbuf, *xA, *xB;
    cudaGetSymbolAddress((void**)&Qn,   g_Qn);
    cudaGetSymbolAddress((void**)&rbuf, g_r);
    cudaGetSymbolAddress((void**)&xA,   g_xA);
    cudaGetSymbolAddress((void**)&xB,   g_xB);

    const int qnBlocks       = Nn / 8;                 // 1250
    const int nodeWarpBlocks = (Nn * 32 + 255) / 256;  // 1250
    const int e4Blocks       = (Ee / 4 + 255) / 256;   // 157

    // ---------------- counting sort of edges by src ---------------------
    zero_kernel<<<(Nn + 1023) / 1024, 1024>>>();
    hist_kernel<<<e4Blocks, 256>>>(ei);
    scan_kernel<<<1, 1024>>>();
    scatter_kernel<<<e4Blocks, 256>>>(ei, ea);

    // ---------------- layer 0 (din=4, input not relu'd) ----------------
    qnaux_kernel<Ff, false><<<qnBlocks, 128>>>(x,  w2[0], rt[0], bs[0], b2[0], Qn, xA, rbuf);
    edge5_kernel<<<nodeWarpBlocks, 256>>>(w1[0], b1[0], Qn, rbuf, xA);

    // ---------------- layer 1 -------------------------------------------
    qnaux_kernel<Hh, true ><<<qnBlocks, 128>>>(xA, w2[1], rt[1], bs[1], b2[1], Qn, xB, rbuf);
    edge5_kernel<<<nodeWarpBlocks, 256>>>(w1[1], b1[1], Qn, rbuf, xB);

    // ---------------- layer 2 -------------------------------------------
    qnaux_kernel<Hh, true ><<<qnBlocks, 128>>>(xB, w2[2], rt[2], bs[2], b2[2], Qn, xA, rbuf);
    edge5_kernel<<<nodeWarpBlocks, 256>>>(w1[2], b1[2], Qn, rbuf, xA);

    // ---------------- FC + log_softmax ----------------------------------
    fc_kernel<<<nodeWarpBlocks, 256>>>(xA, fcw, fcb, out);
}

// round 11
// speedup vs baseline: 1.3081x; 1.2346x over previous
#include <cuda_runtime.h>
#include <math.h>

#define Nn 10000
#define Ee 160000
#define Ff 4
#define Hh 32
#define Cc 4

// ---------------- scratch (device globals; no allocation allowed) -----------
__device__ float g_Qn[Nn * Hh * Hh];       // per-node Q matrices [N, H, H] (40MB)
__device__ float g_r [Nn * Hh];            // per-node b2 contribution r[n,o]
__device__ float g_xA[Nn * Hh];            // ping-pong node features (pre-relu)
__device__ float g_xB[Nn * Hh];
__device__ int    g_cnt[Nn];               // counting sort: histogram
__device__ int    g_cur[Nn];               // counting sort: scatter cursors
__device__ int    g_off[Nn + 1];           // CSR offsets by src
__device__ int    g_sdst[Ee];              // dst sorted by src
__device__ float2 g_sea [Ee];              // edge_attr sorted by src

// ---------------------------------------------------------------------------
__global__ void zero_kernel() {
    int t = blockIdx.x * blockDim.x + threadIdx.x;
    if (t < Nn) { g_cnt[t] = 0; g_cur[t] = 0; }
}

__global__ void hist_kernel(const int* __restrict__ ei) {
    int base = (blockIdx.x * blockDim.x + threadIdx.x) * 4;
#pragma unroll
    for (int j = 0; j < 4; j++) {
        int t = base + j;
        if (t < Ee) atomicAdd(&g_cnt[ei[t]], 1);
    }
}

// warp-shfl scan: 1024 threads x 10 items, 2 barriers total
__global__ void scan_kernel() {
    __shared__ int wsum[32];
    const int tid  = threadIdx.x;
    const int lane = tid & 31, wid = tid >> 5;
    const int base = tid * 10;

    int loc[10];
    int s = 0;
#pragma unroll
    for (int j = 0; j < 10; j++) {
        int idx = base + j;
        int v = (idx < Nn) ? g_cnt[idx] : 0;
        loc[j] = s;
        s += v;
    }
    int t = s;
#pragma unroll
    for (int d = 1; d < 32; d <<= 1) {
        int u = __shfl_up_sync(0xffffffffu, t, d);
        if (lane >= d) t += u;
    }
    if (lane == 31) wsum[wid] = t;
    __syncthreads();
    if (wid == 0) {
        int w = wsum[lane];
#pragma unroll
        for (int d = 1; d < 32; d <<= 1) {
            int u = __shfl_up_sync(0xffffffffu, w, d);
            if (lane >= d) w += u;
        }
        wsum[lane] = w;
    }
    __syncthreads();
    int prefix = t - s + (wid > 0 ? wsum[wid - 1] : 0);
#pragma unroll
    for (int j = 0; j < 10; j++) {
        int idx = base + j;
        if (idx < Nn) g_off[idx] = prefix + loc[j];
    }
    if (tid == 1023) g_off[Nn] = wsum[31];
}

__global__ void scatter_kernel(const int* __restrict__ ei,
                               const float* __restrict__ ea) {
    int base = (blockIdx.x * blockDim.x + threadIdx.x) * 4;
#pragma unroll
    for (int j = 0; j < 4; j++) {
        int t = base + j;
        if (t < Ee) {
            int s = ei[t];
            int p = g_off[s] + atomicAdd(&g_cur[s], 1);
            g_sdst[p] = ei[Ee + t];
            g_sea[p]  = reinterpret_cast<const float2*>(ea)[t];
        }
    }
}

// ---------------------------------------------------------------------------
// layer-0 node init: agg = x·root + bias,  rbuf = x·b2   (din = 4)
// ---------------------------------------------------------------------------
__global__ void aux0_kernel(const float* __restrict__ x,
                            const float* __restrict__ root,
                            const float* __restrict__ bias,
                            const float* __restrict__ b2,
                            float* __restrict__ agg,
                            float* __restrict__ rbuf) {
    int warp = (blockIdx.x * blockDim.x + threadIdx.x) >> 5;
    int lane = threadIdx.x & 31;
    if (warp >= Nn) return;
    float accA = 0.f, accR = 0.f;
#pragma unroll
    for (int i = 0; i < Ff; i++) {
        float xv = x[warp * Ff + i];
        accA = fmaf(xv, root[i * Hh + lane], accA);
        accR = fmaf(xv, b2[i * Hh + lane], accR);
    }
    agg [warp * Hh + lane] = accA + bias[lane];
    rbuf[warp * Hh + lane] = accR;
}

// ---------------------------------------------------------------------------
// layer-0 edge kernel with FOLDED Qn: din=4, so qreg[k] is built on the fly
// from 4 x-values and w2_0 cached in smem (16KB). No g_Qn traffic for layer 0.
// ---------------------------------------------------------------------------
__global__ void edge0_kernel(const float* __restrict__ x,
                             const float* __restrict__ w1,
                             const float* __restrict__ b1,
                             const float* __restrict__ w2,
                             const float* __restrict__ rbuf,
                             float* __restrict__ agg) {
    __shared__ float w2s[Hh * Ff * Hh];        // 16KB: w2_0 [k][i*32+o]
    __shared__ float hs_all[8][32][32];        // 32KB: per-warp h tile
    const int wip  = threadIdx.x >> 5;
    const int n    = (blockIdx.x * blockDim.x + threadIdx.x) >> 5;
    const int lane = threadIdx.x & 31;

    for (int i = threadIdx.x; i < Hh * Ff * Hh; i += 256)
        w2s[i] = w2[i];
    __syncthreads();

    if (n >= Nn) return;
    const int beg = g_off[n], end = g_off[n + 1];
    if (beg == end) return;
    float (*hs)[32] = hs_all[wip];

    const float w1a = w1[lane], w1b = w1[Hh + lane], b1v = b1[lane];

    // build qreg from x (4 vals) and smem w2
    float x0 = x[n * Ff + 0], x1 = x[n * Ff + 1];
    float x2 = x[n * Ff + 2], x3 = x[n * Ff + 3];
    float qreg[Hh];
#pragma unroll
    for (int k = 0; k < Hh; k++) {
        const float* w = w2s + k * (Ff * Hh) + lane;
        qreg[k] = fmaf(x0, w[0], fmaf(x1, w[Hh],
                  fmaf(x2, w[2 * Hh], x3 * w[3 * Hh])));
    }
    const float rsrc = rbuf[n * Hh + lane];

    for (int t = beg; t < end; t += 32) {
        const int m = min(32, end - t);
        float2 eav = make_float2(0.f, 0.f);
        int dstv = 0;
        if (lane < m) { eav = g_sea[t + lane]; dstv = g_sdst[t + lane]; }

        for (int e = 0; e < m; e++) {
            float ea0 = __shfl_sync(0xffffffffu, eav.x, e);
            float ea1 = __shfl_sync(0xffffffffu, eav.y, e);
            hs[e][lane] = fmaxf(fmaf(ea0, w1a, fmaf(ea1, w1b, b1v)), 0.f);
        }
        __syncwarp();

        for (int e = 0; e < m; e++) {
            int dst = __shfl_sync(0xffffffffu, dstv, e);
            const float4* hv = reinterpret_cast<const float4*>(hs[e]);
            float a0 = rsrc, a1 = 0.f, a2 = 0.f, a3 = 0.f;
#pragma unroll
            for (int c = 0; c < 8; c++) {
                float4 h4 = hv[c];
                a0 = fmaf(h4.x, qreg[4 * c    ], a0);
                a1 = fmaf(h4.y, qreg[4 * c + 1], a1);
                a2 = fmaf(h4.z, qreg[4 * c + 2], a2);
                a3 = fmaf(h4.w, qreg[4 * c + 3], a3);
            }
            atomicAdd(&agg[dst * Hh + lane], (a0 + a1) + (a2 + a3));
        }
        __syncwarp();
    }
}

// ---------------------------------------------------------------------------
// fused Qn + aux (f32x2 FMA GEMM), layers 1-2 (din = 32)
// ---------------------------------------------------------------------------
template <int DIN>
__global__ void qnaux_kernel(const float* __restrict__ x,
                             const float* __restrict__ w2,
                             const float* __restrict__ root,
                             const float* __restrict__ bias,
                             const float* __restrict__ b2,
                             float* __restrict__ Qn,
                             float* __restrict__ agg,
                             float* __restrict__ rbuf) {
    __shared__ float2 xs2[8][DIN];
    const int nbase = blockIdx.x * 8;
    const int tid = threadIdx.x;

    for (int idx = tid; idx < 8 * DIN; idx += 128) {
        int t = idx / DIN, i = idx % DIN;
        float v = fmaxf(x[(nbase + t) * DIN + i], 0.f);   // relu on load
        xs2[t][i] = make_float2(v, v);
    }
    __syncthreads();

    const int c0 = tid * 8;
    const int k  = c0 >> 5;
    const int ob = c0 & 31;
    const float* wbase = w2 + k * (DIN * Hh) + ob;

    unsigned long long acc[8][4];
#pragma unroll
    for (int t = 0; t < 8; t++)
#pragma unroll
        for (int p = 0; p < 4; p++) acc[t][p] = 0ULL;

#pragma unroll
    for (int i = 0; i < DIN; i++) {
        ulonglong2 wa = *reinterpret_cast<const ulonglong2*>(wbase + i * Hh);
        ulonglong2 wb = *reinterpret_cast<const ulonglong2*>(wbase + i * Hh + 4);
#pragma unroll
        for (int t = 0; t < 8; t++) {
            unsigned long long xv =
                *reinterpret_cast<const unsigned long long*>(&xs2[t][i]);
            asm("fma.rn.f32x2 %0,%1,%2,%0;" : "+l"(acc[t][0]) : "l"(xv), "l"(wa.x));
            asm("fma.rn.f32x2 %0,%1,%2,%0;" : "+l"(acc[t][1]) : "l"(xv), "l"(wa.y));
            asm("fma.rn.f32x2 %0,%1,%2,%0;" : "+l"(acc[t][2]) : "l"(xv), "l"(wb.x));
            asm("fma.rn.f32x2 %0,%1,%2,%0;" : "+l"(acc[t][3]) : "l"(xv), "l"(wb.y));
        }
    }

#pragma unroll
    for (int t = 0; t < 8; t++) {
        float* dst = Qn + (nbase + t) * (Hh * Hh) + c0;
#pragma unroll
        for (int p = 0; p < 4; p++)
            *reinterpret_cast<unsigned long long*>(dst + p * 2) = acc[t][p];
    }

    for (int it = tid; it < 256; it += 128) {
        int t = it >> 5, o = it & 31;
        float accA = 0.f, accR = 0.f;
#pragma unroll
        for (int i = 0; i < DIN; i++) {
            float xv = xs2[t][i].x;
            accA = fmaf(xv, root[i * Hh + o], accA);
            accR = fmaf(xv, b2  [i * Hh + o], accR);
        }
        agg [(nbase + t) * Hh + o] = accA + bias[o];
        rbuf[(nbase + t) * Hh + o] = accR;
    }
}

// ---------------------------------------------------------------------------
// edge stage (layers 1-2), src-sorted: one warp per node, 32-edge tiles,
// scalar atomicAdd scatter (proven fastest: R3 = 172.8us).
// ---------------------------------------------------------------------------
__global__ void edge3_kernel(const float* __restrict__ w1,
                             const float* __restrict__ b1,
                             const float* __restrict__ Qn,
                             const float* __restrict__ rbuf,
                             float* __restrict__ agg) {
    __shared__ float hs_all[8][32][32];        // 32KB: per-warp h tile
    const int wip  = threadIdx.x >> 5;
    const int n    = (blockIdx.x * blockDim.x + threadIdx.x) >> 5;
    const int lane = threadIdx.x & 31;
    if (n >= Nn) return;
    const int beg = g_off[n], end = g_off[n + 1];
    if (beg == end) return;
    float (*hs)[32] = hs_all[wip];

    const float w1a = w1[lane], w1b = w1[Hh + lane], b1v = b1[lane];

    float qreg[Hh];
    const float* __restrict__ q = Qn + n * (Hh * Hh) + lane;
#pragma unroll
    for (int k = 0; k < Hh; k++) qreg[k] = q[k * Hh];
    const float rsrc = rbuf[n * Hh + lane];

    for (int t = beg; t < end; t += 32) {
        const int m = min(32, end - t);
        float2 eav = make_float2(0.f, 0.f);
        int dstv = 0;
        if (lane < m) { eav = g_sea[t + lane]; dstv = g_sdst[t + lane]; }

        for (int e = 0; e < m; e++) {
            float ea0 = __shfl_sync(0xffffffffu, eav.x, e);
            float ea1 = __shfl_sync(0xffffffffu, eav.y, e);
            hs[e][lane] = fmaxf(fmaf(ea0, w1a, fmaf(ea1, w1b, b1v)), 0.f);
        }
        __syncwarp();

        for (int e = 0; e < m; e++) {
            int dst = __shfl_sync(0xffffffffu, dstv, e);
            const float4* hv = reinterpret_cast<const float4*>(hs[e]);
            float a0 = rsrc, a1 = 0.f, a2 = 0.f, a3 = 0.f;
#pragma unroll
            for (int c = 0; c < 8; c++) {
                float4 h4 = hv[c];
                a0 = fmaf(h4.x, qreg[4 * c    ], a0);
                a1 = fmaf(h4.y, qreg[4 * c + 1], a1);
                a2 = fmaf(h4.z, qreg[4 * c + 2], a2);
                a3 = fmaf(h4.w, qreg[4 * c + 3], a3);
            }
            atomicAdd(&agg[dst * Hh + lane], (a0 + a1) + (a2 + a3));
        }
        __syncwarp();
    }
}

// ---------------------------------------------------------------------------
__global__ void fc_kernel(const float* __restrict__ xr,
                          const float* __restrict__ fcw,
                          const float* __restrict__ fcb,
                          float* __restrict__ out) {
    int warp = (blockIdx.x * blockDim.x + threadIdx.x) >> 5;
    int lane = threadIdx.x & 31;
    if (warp >= Nn) return;

    float xv = fmaxf(xr[warp * Hh + lane], 0.f);
    float lg[Cc];
#pragma unroll
    for (int c = 0; c < Cc; c++) {
        float p = xv * fcw[lane * Cc + c];
#pragma unroll
        for (int s = 16; s > 0; s >>= 1)
            p += __shfl_xor_sync(0xffffffffu, p, s);
        lg[c] = p + fcb[c];
    }
    float m = fmaxf(fmaxf(lg[0], lg[1]), fmaxf(lg[2], lg[3]));
    float se = 0.f;
#pragma unroll
    for (int c = 0; c < Cc; c++) se += __expf(lg[c] - m);
    float lse = m + __logf(se);
    if (lane < Cc) out[warp * Cc + lane] = lg[lane] - lse;
}

// ---------------------------------------------------------------------------
extern "C" void kernel_launch(void* const* d_in, const int* in_sizes, int n_in,
                              void* d_out, int out_size) {
    (void)in_sizes; (void)n_in; (void)out_size;

    const float* x  = (const float*)d_in[0];
    const int*   ei = (const int*)  d_in[1];
    const float* ea = (const float*)d_in[2];
    const float* w1[3];  const float* b1[3];  const float* w2[3];
    const float* b2[3];  const float* rt[3];  const float* bs[3];
    for (int l = 0; l < 3; l++) {
        w1[l] = (const float*)d_in[3 + 6 * l + 0];
        b1[l] = (const float*)d_in[3 + 6 * l + 1];
        w2[l] = (const float*)d_in[3 + 6 * l + 2];
        b2[l] = (const float*)d_in[3 + 6 * l + 3];
        rt[l] = (const float*)d_in[3 + 6 * l + 4];
        bs[l] = (const float*)d_in[3 + 6 * l + 5];
    }
    const float* fcw = (const float*)d_in[21];
    const float* fcb = (const float*)d_in[22];
    float* out = (float*)d_out;

    float *Qn, *rbuf, *xA, *xB;
    cudaGetSymbolAddress((void**)&Qn,   g_Qn);
    cudaGetSymbolAddress((void**)&rbuf, g_r);
    cudaGetSymbolAddress((void**)&xA,   g_xA);
    cudaGetSymbolAddress((void**)&xB,   g_xB);

    const int qnBlocks       = Nn / 8;                 // 1250
    const int nodeWarpBlocks = (Nn * 32 + 255) / 256;  // 1250
    const int e4Blocks       = (Ee / 4 + 255) / 256;   // 157

    // ---------------- counting sort of edges by src ---------------------
    zero_kernel<<<(Nn + 1023) / 1024, 1024>>>();
    hist_kernel<<<e4Blocks, 256>>>(ei);
    scan_kernel<<<1, 1024>>>();
    scatter_kernel<<<e4Blocks, 256>>>(ei, ea);

    // ---------------- layer 0: Qn folded into the edge kernel -----------
    aux0_kernel<<<nodeWarpBlocks, 256>>>(x, rt[0], bs[0], b2[0], xA, rbuf);
    edge0_kernel<<<nodeWarpBlocks, 256>>>(x, w1[0], b1[0], w2[0], rbuf, xA);

    // ---------------- layer 1 -------------------------------------------
    qnaux_kernel<Hh><<<qnBlocks, 128>>>(xA, w2[1], rt[1], bs[1], b2[1], Qn, xB, rbuf);
    edge3_kernel<<<nodeWarpBlocks, 256>>>(w1[1], b1[1], Qn, rbuf, xB);

    // ---------------- layer 2 -------------------------------------------
    qnaux_kernel<Hh><<<qnBlocks, 128>>>(xB, w2[2], rt[2], bs[2], b2[2], Qn, xA, rbuf);
    edge3_kernel<<<nodeWarpBlocks, 256>>>(w1[2], b1[2], Qn, rbuf, xA);

    // ---------------- FC + log_softmax ----------------------------------
    fc_kernel<<<nodeWarpBlocks, 256>>>(xA, fcw, fcb, out);
}